// round 1
// baseline (speedup 1.0000x reference)
#include <cuda_runtime.h>
#include <math.h>

#define NN    50000
#define DD    128
#define EADJ  800000
#define EPRED 500000
#define BNEPS 1e-5f

// ---------------- scratch (static device globals; no runtime allocation) ----
__device__ float g_support[NN * DD];   // h @ W
__device__ float g_tmp[NN * DD];       // h @ W_self + b, then += spmm
__device__ float g_h1[NN * DD];        // layer-1 output
__device__ float g_h2[NN * DD];        // layer-2 output
__device__ float g_stats[2 * DD];      // per-column sum / sumsq
__device__ float g_s1[NN];             // node scores vs Wc[:128]
__device__ float g_s2[NN];             // node scores vs Wc[128:]

// ---------------- fused dual GEMM: support = A@W ; tmp = A@Wself + b --------
// grid.x = row tiles of 64, grid.y in [0,4): y<2 -> W/support, y>=2 -> Wself/tmp
__global__ __launch_bounds__(256) void gemm_dual(
    const float* __restrict__ A,
    const float* __restrict__ W,
    const float* __restrict__ Wself,
    const float* __restrict__ bias,
    float* __restrict__ support,
    float* __restrict__ outtmp)
{
    __shared__ float As[64][68];   // padded to avoid store conflicts
    __shared__ float Bs[64][64];

    const int by      = blockIdx.y;
    const float* B    = (by < 2) ? W : Wself;
    const int colbase = (by & 1) * 64;
    float* Out        = (by < 2) ? support : outtmp;
    const int m0      = blockIdx.x * 64;
    const int tid     = threadIdx.x;
    const int tx      = tid & 15;
    const int ty      = tid >> 4;

    float acc[4][4];
#pragma unroll
    for (int i = 0; i < 4; i++)
#pragma unroll
        for (int j = 0; j < 4; j++) acc[i][j] = 0.0f;

    for (int kc = 0; kc < DD; kc += 64) {
        // A chunk: 64 rows x 64 k
#pragma unroll
        for (int i = 0; i < 4; i++) {
            int idx = tid + i * 256;
            int row = idx >> 4;
            int kv  = (idx & 15) << 2;
            float4 v = make_float4(0.f, 0.f, 0.f, 0.f);
            int gr = m0 + row;
            if (gr < NN) v = *(const float4*)(A + (size_t)gr * DD + kc + kv);
            *(float4*)(&As[row][kv]) = v;
        }
        // B chunk: 64 k x 64 cols
#pragma unroll
        for (int i = 0; i < 4; i++) {
            int idx = tid + i * 256;
            int k   = idx >> 4;
            int cv  = (idx & 15) << 2;
            *(float4*)(&Bs[k][cv]) = *(const float4*)(B + (kc + k) * DD + colbase + cv);
        }
        __syncthreads();

#pragma unroll 16
        for (int k = 0; k < 64; k++) {
            float4 bv = *(const float4*)(&Bs[k][tx << 2]);
            float a0 = As[(ty << 2) + 0][k];
            float a1 = As[(ty << 2) + 1][k];
            float a2 = As[(ty << 2) + 2][k];
            float a3 = As[(ty << 2) + 3][k];
            acc[0][0] += a0 * bv.x; acc[0][1] += a0 * bv.y; acc[0][2] += a0 * bv.z; acc[0][3] += a0 * bv.w;
            acc[1][0] += a1 * bv.x; acc[1][1] += a1 * bv.y; acc[1][2] += a1 * bv.z; acc[1][3] += a1 * bv.w;
            acc[2][0] += a2 * bv.x; acc[2][1] += a2 * bv.y; acc[2][2] += a2 * bv.z; acc[2][3] += a2 * bv.w;
            acc[3][0] += a3 * bv.x; acc[3][1] += a3 * bv.y; acc[3][2] += a3 * bv.z; acc[3][3] += a3 * bv.w;
        }
        __syncthreads();
    }

    float4 bfrag = make_float4(0.f, 0.f, 0.f, 0.f);
    if (by >= 2) bfrag = *(const float4*)(bias + colbase + (tx << 2));

#pragma unroll
    for (int i = 0; i < 4; i++) {
        int gr = m0 + (ty << 2) + i;
        if (gr < NN) {
            float4 r;
            r.x = acc[i][0] + bfrag.x;
            r.y = acc[i][1] + bfrag.y;
            r.z = acc[i][2] + bfrag.z;
            r.w = acc[i][3] + bfrag.w;
            *(float4*)(Out + (size_t)gr * DD + colbase + (tx << 2)) = r;
        }
    }
}

// ---------------- SpMM scatter: tmp[row] += val * support[col] --------------
__global__ __launch_bounds__(256) void spmm_scatter(
    const int* __restrict__ rows, const int* __restrict__ cols,
    const float* __restrict__ vals,
    const float* __restrict__ S, float* __restrict__ Out)
{
    int gid = blockIdx.x * blockDim.x + threadIdx.x;
    int e   = gid >> 5;
    if (e >= EADJ) return;
    int dg  = (gid & 31) << 2;           // column group of 4
    int c   = cols[e];
    int r   = rows[e];
    float v = vals[e];
    float4 s = *(const float4*)(S + (size_t)c * DD + dg);
    float4 add = make_float4(v * s.x, v * s.y, v * s.z, v * s.w);
#if __CUDA_ARCH__ >= 900
    atomicAdd((float4*)(Out + (size_t)r * DD + dg), add);
#else
    float* p = Out + (size_t)r * DD + dg;
    atomicAdd(p + 0, add.x); atomicAdd(p + 1, add.y);
    atomicAdd(p + 2, add.z); atomicAdd(p + 3, add.w);
#endif
}

// ---------------- BN statistics ---------------------------------------------
__global__ void zero_stats()
{
    int t = threadIdx.x;
    if (t < 2 * DD) g_stats[t] = 0.0f;
}

__global__ __launch_bounds__(128) void col_stats(const float* __restrict__ X)
{
    int col = threadIdx.x;           // 128 threads = 128 columns
    int r0  = blockIdx.x * 128;
    int rend = r0 + 128;
    if (rend > NN) rend = NN;
    float s = 0.f, sq = 0.f;
    for (int r = r0; r < rend; r++) {
        float v = X[(size_t)r * DD + col];
        s  += v;
        sq += v * v;
    }
    atomicAdd(&g_stats[col], s);
    atomicAdd(&g_stats[DD + col], sq);
}

// ---------------- BN normalize + ReLU ---------------------------------------
__global__ __launch_bounds__(256) void bn_relu(
    const float* __restrict__ X,
    const float* __restrict__ gamma,
    const float* __restrict__ beta,
    float* __restrict__ Hout)
{
    int gid = blockIdx.x * blockDim.x + threadIdx.x;     // per float4
    if (gid >= NN * DD / 4) return;
    int col = (gid & 31) << 2;
    size_t off = (size_t)gid << 2;
    float4 v = *(const float4*)(X + off);
    const float invN = 1.0f / (float)NN;
    float4 r;
    {
        float m = g_stats[col + 0] * invN;
        float var = g_stats[DD + col + 0] * invN - m * m;
        r.x = fmaxf(0.f, (v.x - m) * rsqrtf(var + BNEPS) * gamma[col + 0] + beta[col + 0]);
    }
    {
        float m = g_stats[col + 1] * invN;
        float var = g_stats[DD + col + 1] * invN - m * m;
        r.y = fmaxf(0.f, (v.y - m) * rsqrtf(var + BNEPS) * gamma[col + 1] + beta[col + 1]);
    }
    {
        float m = g_stats[col + 2] * invN;
        float var = g_stats[DD + col + 2] * invN - m * m;
        r.z = fmaxf(0.f, (v.z - m) * rsqrtf(var + BNEPS) * gamma[col + 2] + beta[col + 2]);
    }
    {
        float m = g_stats[col + 3] * invN;
        float var = g_stats[DD + col + 3] * invN - m * m;
        r.w = fmaxf(0.f, (v.w - m) * rsqrtf(var + BNEPS) * gamma[col + 3] + beta[col + 3]);
    }
    *(float4*)(Hout + off) = r;
}

// ---------------- per-node edge scores: s1/s2 = (h2+x) . Wc halves ----------
__global__ __launch_bounds__(256) void node_scores(
    const float* __restrict__ H,
    const float* __restrict__ X,
    const float* __restrict__ Wc)
{
    int warp = (blockIdx.x * blockDim.x + threadIdx.x) >> 5;
    int lane = threadIdx.x & 31;
    if (warp >= NN) return;
    size_t off = (size_t)warp * DD + (lane << 2);
    float4 h = *(const float4*)(H + off);
    float4 x = *(const float4*)(X + off);
    float4 w1 = *(const float4*)(Wc + (lane << 2));
    float4 w2 = *(const float4*)(Wc + DD + (lane << 2));
    float e0 = h.x + x.x, e1 = h.y + x.y, e2 = h.z + x.z, e3 = h.w + x.w;
    float s1 = e0 * w1.x + e1 * w1.y + e2 * w1.z + e3 * w1.w;
    float s2 = e0 * w2.x + e1 * w2.y + e2 * w2.z + e3 * w2.w;
#pragma unroll
    for (int o = 16; o; o >>= 1) {
        s1 += __shfl_xor_sync(0xFFFFFFFFu, s1, o);
        s2 += __shfl_xor_sync(0xFFFFFFFFu, s2, o);
    }
    if (lane == 0) {
        g_s1[warp] = s1;
        g_s2[warp] = s2;
    }
}

// ---------------- edge prediction -------------------------------------------
__global__ __launch_bounds__(256) void edge_pred(
    const int* __restrict__ ei,
    const float* __restrict__ bc,
    float* __restrict__ out)
{
    int e = blockIdx.x * blockDim.x + threadIdx.x;
    if (e >= EPRED) return;
    float z = g_s1[ei[e]] + g_s2[ei[e + EPRED]] + bc[0];
    out[e] = 1.0f / (1.0f + expf(-z));
}

// ---------------- launch ----------------------------------------------------
extern "C" void kernel_launch(void* const* d_in, const int* in_sizes, int n_in,
                              void* d_out, int out_size)
{
    const float* x       = (const float*)d_in[0];
    const int*   adj_row = (const int*)d_in[1];
    const int*   adj_col = (const int*)d_in[2];
    const float* adj_val = (const float*)d_in[3];
    const int*   eidx    = (const int*)d_in[4];
    const float* W       = (const float*)d_in[5];
    const float* Wself   = (const float*)d_in[6];
    const float* b       = (const float*)d_in[7];
    const float* gamma   = (const float*)d_in[8];
    const float* beta    = (const float*)d_in[9];
    const float* Wc      = (const float*)d_in[10];
    const float* bc      = (const float*)d_in[11];
    float* out           = (float*)d_out;

    float *support, *tmp, *h1, *h2;
    cudaGetSymbolAddress((void**)&support, g_support);
    cudaGetSymbolAddress((void**)&tmp,     g_tmp);
    cudaGetSymbolAddress((void**)&h1,      g_h1);
    cudaGetSymbolAddress((void**)&h2,      g_h2);

    const dim3 gemm_grid((NN + 63) / 64, 4);
    const int spmm_blocks = (EADJ * 32 + 255) / 256;
    const int stat_blocks = (NN + 127) / 128;
    const int bn_blocks   = (NN * DD / 4 + 255) / 256;

    const float* hin = x;
    float* houts[2] = { h1, h2 };
    for (int l = 0; l < 2; l++) {
        gemm_dual<<<gemm_grid, 256>>>(hin, W + l * DD * DD, Wself + l * DD * DD,
                                      b + l * DD, support, tmp);
        spmm_scatter<<<spmm_blocks, 256>>>(adj_row, adj_col, adj_val, support, tmp);
        zero_stats<<<1, 256>>>();
        col_stats<<<stat_blocks, 128>>>(tmp);
        bn_relu<<<bn_blocks, 256>>>(tmp, gamma + l * DD, beta + l * DD, houts[l]);
        hin = houts[l];
    }

    node_scores<<<(NN * 32 + 255) / 256, 256>>>(h2, x, Wc);
    edge_pred<<<(EPRED + 255) / 256, 256>>>(eidx, bc, out);
}